// round 10
// baseline (speedup 1.0000x reference)
#include <cuda_runtime.h>
#include <stdint.h>

#define LL 401
#define BB 256
#define PLANE 160801             // LL*LL (odd!)
#define NPAIR 201                // pairs per row
#define NTH (LL * NPAIR)         // 80601 threads of work
#define NBX 315                  // ceil(NTH/256)
#define CHB 32                   // batches per chunk
#define NCHY (BB / CHB)          // 8
#define NBLK (NBX * NCHY)        // 2520

// ---------------- device-global scratch (no allocations allowed) -------------
__device__ double g_bin[LL];             // per-distance-bin sum of cm
__device__ double g_W;                   // sum cm * same * maskf
__device__ double g_NC;                  // sum relu(cm) * non_conv
__device__ double g_bSame[BB];           // per-batch same*maskf count
__device__ double g_bNc[BB];             // per-batch non_conv count
__device__ unsigned char g_Q[2][BB * LL + 8]; // copy s: byte (y+s) = P[y]
__device__ unsigned char g_PT[LL * 256]; // [i][b] transposed P
__device__ unsigned g_done;              // last-block-done counter

// ---------------- prep: pack bytes + copies + per-batch counts ---------------
__global__ void k_prep(const float2* __restrict__ logits, const int* __restrict__ ctcf) {
    int b = blockIdx.x, t = threadIdx.x;
    if (b == 0) {                         // zero accumulators (graph is replayed)
        if (t < LL) g_bin[t] = 0.0;
        if (t == LL) { g_W = 0.0; g_NC = 0.0; }
    }
    __shared__ unsigned char sc[LL];
    __shared__ unsigned long long shw[16];
    unsigned long long pack = 0ull;
    if (t < LL) {
        int idx = b * LL + t;
        float2 l = logits[idx];
        int o = ctcf[idx];
        unsigned c = (l.y > l.x) ? 1u : 0u;      // argmax of 2 logits (tie -> 0)
        unsigned A = (o != 0) ? 1u : 0u;
        unsigned F = (o == 1) ? 1u : 0u;
        unsigned R = (o == -1) ? 1u : 0u;
        unsigned char byte = (unsigned char)(c | (A << 1) | (F << 2) | (R << 3));
        g_Q[0][idx]     = byte;
        g_Q[1][idx + 1] = byte;
        g_PT[t * 256 + b] = byte;
        sc[t] = (unsigned char)c;
        pack = (unsigned long long)c
             | ((unsigned long long)F << 24)
             | ((unsigned long long)R << 36)
             | ((unsigned long long)A << 48);
    }
    __syncthreads();
    if (t < LL - 1) pack |= ((unsigned long long)(sc[t] == sc[t + 1] ? 1u : 0u)) << 12;

#pragma unroll
    for (int o = 16; o > 0; o >>= 1) pack += __shfl_down_sync(0xffffffffu, pack, o);
    if ((t & 31) == 0) shw[t >> 5] = pack;
    __syncthreads();
    if (t == 0) {
        unsigned long long s = 0;
        for (int w = 0; w < 16; w++) s += shw[w];
        double n1  = (double)(s & 0xFFFull);
        double adj = (double)((s >> 12) & 0xFFFull);
        double F   = (double)((s >> 24) & 0xFFFull);
        double R   = (double)((s >> 36) & 0xFFFull);
        double A   = (double)((s >> 48) & 0xFFFull);
        double n0  = (double)LL - n1;
        g_bSame[b] = n0 * n0 + n1 * n1 - (double)LL - 2.0 * adj;  // same & |i-j|>=2
        g_bNc[b]   = A * A - F * R;                               // non_conv count
    }
}

// ---------------- block reduction over 256 threads --------------------------
__device__ __forceinline__ double blockRed256(double v, double* sh) {
    int t = threadIdx.x;
#pragma unroll
    for (int o = 16; o > 0; o >>= 1) v += __shfl_down_sync(0xffffffffu, v, o);
    if ((t & 31) == 0) sh[t >> 5] = v;
    __syncthreads();
    double r;
    if (t < 32) {
        double w = (t < 8) ? sh[t] : 0.0;
#pragma unroll
        for (int o = 4; o > 0; o >>= 1) w += __shfl_down_sync(0xffffffffu, w, o);
        if (t == 0) sh[0] = w;
    }
    __syncthreads();
    r = sh[0];
    __syncthreads();
    return r;
}

// ---------------- main pass (float2, E/O parity streams) + finalize ----------
__global__ void __launch_bounds__(256, 4) k_main(const float* __restrict__ cm,
                                                 float* __restrict__ out) {
    int tid = threadIdx.x;
    int flat = blockIdx.x * 256 + tid;
    bool active = flat < NTH;
    int f = active ? flat : 0;
    int i = f / NPAIR;
    int p = f - i * NPAIR;
    int iA = i & 1;
    int j0 = 2 * p;
    int dM = abs(i - (j0 - 1)), d0 = abs(i - j0), dP = abs(i - (j0 + 1));
    bool vM = p > 0, vP = p < 200;
    bool w0a = active && (d0 >= 2);
    bool wMa = active && vM && (dM >= 2);
    bool wPa = active && vP && (dP >= 2);
    bool n0a = active;
    bool nMa = active && vM;
    bool nPa = active && vP;

    int b0 = blockIdx.y * CHB;            // multiple of 32 (even)
    int bE = b0 + iA;                     // (bE + i) even  -> window starts at j0
    int bO = b0 + (iA ^ 1);               // (bO + i) odd   -> window starts at j0-1
    const float* pE = cm + (size_t)bE * PLANE + (size_t)i * LL + j0;       // 8B-aligned
    const float* pO = cm + (size_t)bO * PLANE + (size_t)i * LL + j0 - 1;   // 8B-aligned
    const unsigned char* qE = g_Q[iA] + bE * LL + j0 + iA;                 // 2B-aligned
    const unsigned char* qO = g_Q[iA] + bO * LL + j0 - 1 + iA;             // 2B-aligned
    const unsigned char* pc = g_PT + i * 256 + b0;                         // 4B-aligned
    int shE = 8 * iA, shO = 8 * (iA ^ 1);

    float accB0 = 0.f, accB1 = 0.f, accB2 = 0.f, accW = 0.f, accNC = 0.f;

#define NCTEST(ci, cj) ((((ci) & (cj) & 2u) != 0u) && !((((ci) & 4u) != 0u) && (((cj) & 8u) != 0u)))
#define PROC_E(v, cw, ci) {                                              \
    unsigned cjx = (cw) & 0xFFu, cjy = ((cw) >> 8) & 0xFFu;              \
    accB1 += (v).x; accB2 += (v).y;                                      \
    if (w0a && !(((ci) ^ cjx) & 1u)) accW += (v).x;                      \
    if (wPa && !(((ci) ^ cjy) & 1u)) accW += (v).y;                      \
    if (n0a && NCTEST(ci, cjx)) accNC += fmaxf((v).x, 0.f);              \
    if (nPa && NCTEST(ci, cjy)) accNC += fmaxf((v).y, 0.f); }
#define PROC_O(v, cw, ci) {                                              \
    unsigned cjx = (cw) & 0xFFu, cjy = ((cw) >> 8) & 0xFFu;              \
    accB0 += (v).x; accB1 += (v).y;                                      \
    if (wMa && !(((ci) ^ cjx) & 1u)) accW += (v).x;                      \
    if (w0a && !(((ci) ^ cjy) & 1u)) accW += (v).y;                      \
    if (nMa && NCTEST(ci, cjx)) accNC += fmaxf((v).x, 0.f);              \
    if (n0a && NCTEST(ci, cjy)) accNC += fmaxf((v).y, 0.f); }

#pragma unroll
    for (int g = 0; g < CHB / 4; g++) {
        float2 vE0 = *(const float2*)(pE);
        float2 vO0 = *(const float2*)(pO);
        float2 vE1 = *(const float2*)(pE + 2 * PLANE);
        float2 vO1 = *(const float2*)(pO + 2 * PLANE);
        unsigned cE0 = *(const unsigned short*)(qE);
        unsigned cO0 = *(const unsigned short*)(qO);
        unsigned cE1 = *(const unsigned short*)(qE + 2 * LL);
        unsigned cO1 = *(const unsigned short*)(qO + 2 * LL);
        unsigned cb  = *(const unsigned*)(pc);
        pE += (size_t)4 * PLANE; pO += (size_t)4 * PLANE;
        qE += 4 * LL; qO += 4 * LL; pc += 4;

        unsigned ciE0 = (cb >> shE) & 0xFFu;          // batch bE
        unsigned ciO0 = (cb >> shO) & 0xFFu;          // batch bO
        unsigned ciE1 = (cb >> (shE + 16)) & 0xFFu;   // batch bE+2
        unsigned ciO1 = (cb >> (shO + 16)) & 0xFFu;   // batch bO+2

        PROC_E(vE0, cE0, ciE0)
        PROC_O(vO0, cO0, ciO0)
        PROC_E(vE1, cE1, ciE1)
        PROC_O(vO1, cO1, ciO1)
    }
#undef PROC_E
#undef PROC_O
#undef NCTEST

    // ---- per-thread bin atomics (bins were register-resident) ----
    if (active) {
        atomicAdd(&g_bin[d0], (double)accB1);
        if (vM) atomicAdd(&g_bin[dM], (double)accB0);
        if (vP) atomicAdd(&g_bin[dP], (double)accB2);
    }

    // ---- scalar reductions -> 2 double atomics per block ----
#pragma unroll
    for (int o = 16; o > 0; o >>= 1) {
        accW  += __shfl_down_sync(0xffffffffu, accW,  o);
        accNC += __shfl_down_sync(0xffffffffu, accNC, o);
    }
    __shared__ double sW[8], sN[8];
    if ((tid & 31) == 0) { sW[tid >> 5] = accW; sN[tid >> 5] = accNC; }
    __syncthreads();
    if (tid == 0) {
        double w = 0.0, nn = 0.0;
#pragma unroll
        for (int z = 0; z < 8; z++) { w += sW[z]; nn += sN[z]; }
        atomicAdd(&g_W, w);
        atomicAdd(&g_NC, nn);
    }

    // ---------- last-block-done: fused finalize ----------
    __shared__ bool isLast;
    __threadfence();
    if (tid == 0) {
        unsigned v0 = atomicAdd(&g_done, 1u);
        isLast = (v0 == (unsigned)(NBLK - 1));
    }
    __syncthreads();
    if (!isLast) return;
    if (tid == 0) g_done = 0;            // reset for next graph replay
    __threadfence();

    {
        __shared__ double sh[8];
        int t = tid;
        int t1 = t + 256;

        double bs0 = (t  < LL) ? g_bin[t]  : 0.0;
        double bs1 = (t1 < LL) ? g_bin[t1] : 0.0;
        double cnt0 = (t == 0) ? (double)LL : 2.0 * (double)(LL - t);
        double cnt1 = 2.0 * (double)(LL - t1);
        double mean0 = bs0 / (cnt0 * (double)BB);
        double mean1 = (t1 < LL) ? bs1 / (cnt1 * (double)BB) : 0.0;
        bool va0 = (t  < LL) && (t  >= 2) && isfinite(mean0) && (mean0 > 0.0);
        bool va1 = (t1 < LL)              && isfinite(mean1) && (mean1 > 0.0);
        double w0 = va0 ? 1.0 : 0.0, w1 = va1 ? 1.0 : 0.0;
        double ld0 = log(fmax((double)t, 1.0));
        double ld1 = log((double)t1);
        double lp0 = log((va0 ? mean0 : 1.0) + 1e-6);
        double lp1 = log((va1 ? mean1 : 1.0) + 1e-6);

        double n     = blockRed256(w0 + w1, sh);
        double sx    = blockRed256(w0 * ld0 + w1 * ld1, sh);
        double sy    = blockRed256(w0 * lp0 + w1 * lp1, sh);
        double tm    = blockRed256(((t >= 2 && t < LL) ? bs0 : 0.0) +
                                   ((t1 < LL) ? bs1 : 0.0), sh);
        double sameC = blockRed256(g_bSame[t], sh);     // exactly 256 batches
        double ncC   = blockRed256(g_bNc[t], sh);

        double nsafe = fmax(n, 1.0);
        double xm = sx / nsafe, ym = sy / nsafe;
        double num = blockRed256(w0 * (ld0 - xm) * (lp0 - ym) +
                                 w1 * (ld1 - xm) * (lp1 - ym), sh);
        double den = blockRed256(w0 * (ld0 - xm) * (ld0 - xm) +
                                 w1 * (ld1 - xm) * (ld1 - xm), sh) + 1e-8;

        if (t == 0) {
            double slope = num / den;
            double dist  = (n >= 5.0) ? (slope + 0.85) * (slope + 0.85) : 0.0;

            double ctcf = (ncC < 1.0) ? 0.0 : g_NC / (ncC + 1e-6);

            double diffC   = (double)BB * ((double)LL * LL - 3.0 * LL + 2.0) - sameC;
            double within  = g_W / fmax(sameC, 1.0);
            double between = (tm - g_W) / fmax(diffC, 1.0);
            double ratio   = within / (fabs(between) + 1e-6);
            double comp    = fmax(0.0, 1.5 - ratio);

            out[0] = (float)dist;
            out[1] = (float)ctcf;
            out[2] = (float)comp;
            out[3] = (float)(dist + 0.5 * ctcf + 0.5 * comp);
        }
    }
}

// ---------------- launch ----------------------------------------------------
extern "C" void kernel_launch(void* const* d_in, const int* in_sizes, int n_in,
                              void* d_out, int out_size) {
    const float* cm      = (const float*)d_in[0];
    const float2* logits = (const float2*)d_in[1];
    const int*   ctcf    = (const int*)d_in[2];
    float* out = (float*)d_out;

    k_prep<<<BB, 512>>>(logits, ctcf);
    k_main<<<dim3(NBX, NCHY), 256>>>(cm, out);
}

// round 11
// speedup vs baseline: 3.9646x; 3.9646x over previous
#include <cuda_runtime.h>
#include <stdint.h>

#define LL 401
#define BB 256
#define PLANE 160801             // LL*LL
#define PROWS 51                 // rows per panel
#define NPANEL 8                 // ceil(401/51)
#define NBLK (BB * NPANEL)       // 2048

// ---------------- device-global scratch (no allocations allowed) -------------
__device__ double g_bin[LL];             // per-distance-bin sum of cm
__device__ double g_W;                   // sum cm * same * maskf
__device__ double g_NC;                  // sum relu(cm) * non_conv
__device__ double g_bSame[BB];           // per-batch same*maskf count
__device__ double g_bNc[BB];             // per-batch non_conv count
__device__ unsigned char g_P[BB * LL + 64]; // [b*401+pos] bit0=comp b1=any b2=f b3=r (+pad)
__device__ unsigned g_done;              // last-block-done counter

// ---------------- prep: pack bytes + per-batch counts + zero globals ---------
__global__ void k_prep(const float2* __restrict__ logits, const int* __restrict__ ctcf) {
    int b = blockIdx.x, t = threadIdx.x;
    if (b == 0) {                         // zero accumulators (graph is replayed)
        if (t < LL) g_bin[t] = 0.0;
        if (t == LL) { g_W = 0.0; g_NC = 0.0; }
    }
    __shared__ unsigned char sc[LL];
    __shared__ unsigned long long shw[16];
    unsigned long long pack = 0ull;
    if (t < LL) {
        int idx = b * LL + t;
        float2 l = logits[idx];
        int o = ctcf[idx];
        unsigned c = (l.y > l.x) ? 1u : 0u;      // argmax of 2 logits (tie -> 0)
        unsigned A = (o != 0) ? 1u : 0u;
        unsigned F = (o == 1) ? 1u : 0u;
        unsigned R = (o == -1) ? 1u : 0u;
        g_P[idx] = (unsigned char)(c | (A << 1) | (F << 2) | (R << 3));
        sc[t] = (unsigned char)c;
        pack = (unsigned long long)c
             | ((unsigned long long)F << 24)
             | ((unsigned long long)R << 36)
             | ((unsigned long long)A << 48);
    }
    __syncthreads();
    if (t < LL - 1) pack |= ((unsigned long long)(sc[t] == sc[t + 1] ? 1u : 0u)) << 12;

#pragma unroll
    for (int o = 16; o > 0; o >>= 1) pack += __shfl_down_sync(0xffffffffu, pack, o);
    if ((t & 31) == 0) shw[t >> 5] = pack;
    __syncthreads();
    if (t == 0) {
        unsigned long long s = 0;
        for (int w = 0; w < 16; w++) s += shw[w];
        double n1  = (double)(s & 0xFFFull);
        double adj = (double)((s >> 12) & 0xFFFull);
        double F   = (double)((s >> 24) & 0xFFFull);
        double R   = (double)((s >> 36) & 0xFFFull);
        double A   = (double)((s >> 48) & 0xFFFull);
        double n0  = (double)LL - n1;
        g_bSame[b] = n0 * n0 + n1 * n1 - (double)LL - 2.0 * adj;  // same & |i-j|>=2
        g_bNc[b]   = A * A - F * R;                               // non_conv count
    }
}

// ---------------- block reduction over 256 threads --------------------------
__device__ __forceinline__ double blockRed256(double v, double* sh) {
    int t = threadIdx.x;
#pragma unroll
    for (int o = 16; o > 0; o >>= 1) v += __shfl_down_sync(0xffffffffu, v, o);
    if ((t & 31) == 0) sh[t >> 5] = v;
    __syncthreads();
    double r;
    if (t < 32) {
        double w = (t < 8) ? sh[t] : 0.0;
#pragma unroll
        for (int o = 4; o > 0; o >>= 1) w += __shfl_down_sync(0xffffffffu, w, o);
        if (t == 0) sh[0] = w;
    }
    __syncthreads();
    r = sh[0];
    __syncthreads();
    return r;
}

// ---------------- main pass: streaming rows + signed-diagonal smem bins ------
__global__ void __launch_bounds__(256, 5) k_main(const float* __restrict__ cm,
                                                 float* __restrict__ out) {
    __shared__ float sb[8][802];          // per-warp signed-diagonal bins (25.7 KB)
    int tid = threadIdx.x;
    int w = tid >> 5, lane = tid & 31;
    int b = blockIdx.x;                   // plane
    int r0 = blockIdx.y * PROWS;
    int r1 = min(LL, r0 + PROWS);

    // zero per-warp bin arrays
    for (int k = tid; k < 8 * 802; k += 256) ((float*)sb)[k] = 0.f;

    // preload this block's cj bytes: column lane+32c of plane b, c=0..12 (pad-safe)
    const unsigned char* pb = g_P + b * LL;
    unsigned cjp[4] = {0, 0, 0, 0};
#pragma unroll
    for (int c = 0; c < 13; c++)
        cjp[c >> 2] |= (unsigned)pb[32 * c + lane] << (8 * (c & 3));
    __syncthreads();

    float accW = 0.f, accNC = 0.f;
    float* mybin = sb[w];
    const float* rowp = cm + (size_t)b * PLANE + (size_t)(r0 + w) * LL;

    for (int i = r0 + w; i < r1; i += 8, rowp += 8 * LL) {
        unsigned ci = pb[i];
        float v[12];
#pragma unroll
        for (int c = 0; c < 12; c++) v[c] = rowp[32 * c + lane];   // imm-offset batch
        float tv = (lane < 17) ? rowp[384 + lane] : 0.f;
        float* A = mybin + (i + 400 - lane);

#pragma unroll
        for (int c = 0; c < 12; c++) {
            float vv = v[c];
            unsigned cj = (cjp[c >> 2] >> (8 * (c & 3))) & 0xFFu;
            A[-32 * c] += vv;                                      // conflict-free RMW
            int tt = i - 32 * c - lane;                            // i - j
            bool wok = ((unsigned)(tt + 1) > 2u);                  // |i-j| >= 2
            if (wok && !((ci ^ cj) & 1u)) accW += vv;
            if (((ci & cj & 2u) != 0u) && !(((ci & 4u) != 0u) && ((cj & 8u) != 0u)))
                accNC += fmaxf(vv, 0.f);
        }
        // tail chunk j = 384 + lane, active lanes < 17
        if (lane < 17) {
            unsigned cj = (cjp[3]) & 0xFFu;                        // c=12 -> byte 0 of word 3
            A[-384] += tv;
            int tt = i - 384 - lane;
            bool wok = ((unsigned)(tt + 1) > 2u);
            if (wok && !((ci ^ cj) & 1u)) accW += tv;
            if (((ci & cj & 2u) != 0u) && !(((ci & 4u) != 0u) && ((cj & 8u) != 0u)))
                accNC += fmaxf(tv, 0.f);
        }
    }

    __syncthreads();
    // fold per-warp signed bins -> g_bin[d] (d and -d)
    for (int t = tid; t < LL; t += 256) {
        float s = 0.f;
#pragma unroll
        for (int q = 0; q < 8; q++) {
            s += sb[q][400 + t];
            if (t) s += sb[q][400 - t];
        }
        atomicAdd(&g_bin[t], (double)s);
    }

    // scalar reductions -> 2 double atomics per block
#pragma unroll
    for (int o = 16; o > 0; o >>= 1) {
        accW  += __shfl_down_sync(0xffffffffu, accW,  o);
        accNC += __shfl_down_sync(0xffffffffu, accNC, o);
    }
    __shared__ double sW[8], sN[8];
    if ((tid & 31) == 0) { sW[tid >> 5] = accW; sN[tid >> 5] = accNC; }
    __syncthreads();
    if (tid == 0) {
        double ww = 0.0, nn = 0.0;
#pragma unroll
        for (int z = 0; z < 8; z++) { ww += sW[z]; nn += sN[z]; }
        atomicAdd(&g_W, ww);
        atomicAdd(&g_NC, nn);
    }

    // ---------- last-block-done: fused finalize ----------
    __shared__ bool isLast;
    __threadfence();
    if (tid == 0) {
        unsigned v0 = atomicAdd(&g_done, 1u);
        isLast = (v0 == (unsigned)(NBLK - 1));
    }
    __syncthreads();
    if (!isLast) return;
    if (tid == 0) g_done = 0;            // reset for next graph replay
    __threadfence();

    {
        __shared__ double sh[8];
        int t = tid;
        int t1 = t + 256;

        double bs0 = (t  < LL) ? g_bin[t]  : 0.0;
        double bs1 = (t1 < LL) ? g_bin[t1] : 0.0;
        double cnt0 = (t == 0) ? (double)LL : 2.0 * (double)(LL - t);
        double cnt1 = 2.0 * (double)(LL - t1);
        double mean0 = bs0 / (cnt0 * (double)BB);
        double mean1 = (t1 < LL) ? bs1 / (cnt1 * (double)BB) : 0.0;
        bool va0 = (t  < LL) && (t  >= 2) && isfinite(mean0) && (mean0 > 0.0);
        bool va1 = (t1 < LL)              && isfinite(mean1) && (mean1 > 0.0);
        double w0 = va0 ? 1.0 : 0.0, w1 = va1 ? 1.0 : 0.0;
        double ld0 = log(fmax((double)t, 1.0));
        double ld1 = log((double)t1);
        double lp0 = log((va0 ? mean0 : 1.0) + 1e-6);
        double lp1 = log((va1 ? mean1 : 1.0) + 1e-6);

        double n     = blockRed256(w0 + w1, sh);
        double sx    = blockRed256(w0 * ld0 + w1 * ld1, sh);
        double sy    = blockRed256(w0 * lp0 + w1 * lp1, sh);
        double tm    = blockRed256(((t >= 2 && t < LL) ? bs0 : 0.0) +
                                   ((t1 < LL) ? bs1 : 0.0), sh);
        double sameC = blockRed256(g_bSame[t], sh);     // exactly 256 batches
        double ncC   = blockRed256(g_bNc[t], sh);

        double nsafe = fmax(n, 1.0);
        double xm = sx / nsafe, ym = sy / nsafe;
        double num = blockRed256(w0 * (ld0 - xm) * (lp0 - ym) +
                                 w1 * (ld1 - xm) * (lp1 - ym), sh);
        double den = blockRed256(w0 * (ld0 - xm) * (ld0 - xm) +
                                 w1 * (ld1 - xm) * (ld1 - xm), sh) + 1e-8;

        if (t == 0) {
            double slope = num / den;
            double dist  = (n >= 5.0) ? (slope + 0.85) * (slope + 0.85) : 0.0;

            double ctcf = (ncC < 1.0) ? 0.0 : g_NC / (ncC + 1e-6);

            double diffC   = (double)BB * ((double)LL * LL - 3.0 * LL + 2.0) - sameC;
            double within  = g_W / fmax(sameC, 1.0);
            double between = (tm - g_W) / fmax(diffC, 1.0);
            double ratio   = within / (fabs(between) + 1e-6);
            double comp    = fmax(0.0, 1.5 - ratio);

            out[0] = (float)dist;
            out[1] = (float)ctcf;
            out[2] = (float)comp;
            out[3] = (float)(dist + 0.5 * ctcf + 0.5 * comp);
        }
    }
}

// ---------------- launch ----------------------------------------------------
extern "C" void kernel_launch(void* const* d_in, const int* in_sizes, int n_in,
                              void* d_out, int out_size) {
    const float* cm      = (const float*)d_in[0];
    const float2* logits = (const float2*)d_in[1];
    const int*   ctcf    = (const int*)d_in[2];
    float* out = (float*)d_out;

    k_prep<<<BB, 512>>>(logits, ctcf);
    k_main<<<dim3(BB, NPANEL), 256>>>(cm, out);
}